// round 2
// baseline (speedup 1.0000x reference)
#include <cuda_runtime.h>
#include <cstdint>

#define N_HEADS 4
#define OUTC 1024
#define NSLOPE 0.2f

#define MAXNX 9000
#define MAXNC 1000
#define MAXN  (MAXNX + MAXNC)
#define MAXE0 40000
#define MAXE  (MAXE0 + MAXN)

// ------------------------- static scratch (no allocs) -------------------------
__device__ float g_xh[MAXNX * 512];            // MLP hidden
__device__ float g_xc[MAXN * 1024];            // concat features
__device__ float g_xl[MAXN * 4096];            // left projection  (N, H*OUT)
__device__ float g_xr[MAXN * 4096];            // right projection
__device__ float g_outm[MAXN * 1024];          // head-mean aggregated output
__device__ float g_alpha[MAXE * N_HEADS];      // attention logits -> weights (in place)
__device__ int   g_src[MAXE];
__device__ int   g_dst[MAXE];
__device__ int   g_deg[MAXN];
__device__ int   g_off[MAXN + 1];
__device__ int   g_cur[MAXN];
__device__ int   g_csr[MAXE];

// ------------------------- small utility kernels -------------------------
__global__ void zero_int2(int* a, int* b, int n) {
    int i = blockIdx.x * blockDim.x + threadIdx.x;
    if (i < n) { a[i] = 0; b[i] = 0; }
}

__global__ void copy_f4(const float4* __restrict__ src, float4* __restrict__ dst, int n4) {
    int i = blockIdx.x * blockDim.x + threadIdx.x;
    if (i < n4) dst[i] = src[i];
}

// edge_index is int32 (JAX x64 disabled downcasts int64 -> int32)
__global__ void build_edges(const int* __restrict__ ei, int* __restrict__ src,
                            int* __restrict__ dst, int* __restrict__ deg, int E, int N) {
    int e = blockIdx.x * blockDim.x + threadIdx.x;
    int ET = E + N;
    if (e >= ET) return;
    int s, d;
    if (e < E) { s = ei[2 * e]; d = ei[2 * e + 1]; }
    else       { s = d = e - E; }
    src[e] = s;
    dst[e] = d;
    atomicAdd(&deg[d], 1);
}

// single-block exclusive scan over n, 1024 threads
__global__ void scan_excl(const int* __restrict__ deg, int* __restrict__ off, int n) {
    __shared__ int sh[1024];
    __shared__ int carry;
    if (threadIdx.x == 0) carry = 0;
    __syncthreads();
    for (int base = 0; base < n; base += 1024) {
        int i = base + threadIdx.x;
        int v = (i < n) ? deg[i] : 0;
        sh[threadIdx.x] = v;
        __syncthreads();
        #pragma unroll
        for (int ofs = 1; ofs < 1024; ofs <<= 1) {
            int t = (threadIdx.x >= ofs) ? sh[threadIdx.x - ofs] : 0;
            __syncthreads();
            sh[threadIdx.x] += t;
            __syncthreads();
        }
        if (i < n) off[i] = carry + sh[threadIdx.x] - v;  // exclusive
        __syncthreads();
        if (threadIdx.x == 1023) carry += sh[1023];
        __syncthreads();
    }
    if (threadIdx.x == 0) off[n] = carry;
}

__global__ void fill_csr(const int* __restrict__ dst, const int* __restrict__ off,
                         int* __restrict__ cur, int* __restrict__ csr, int ET) {
    int e = blockIdx.x * blockDim.x + threadIdx.x;
    if (e >= ET) return;
    int d = dst[e];
    int p = off[d] + atomicAdd(&cur[d], 1);
    csr[p] = e;
}

// ------------------------- SGEMM: C = A(MxK) @ B(KxN) + bias, optional ReLU ----
// Classic 128x128x8 tile, 256 threads, 8x8 micro-tile, fp32.
// Requires K % 8 == 0 and N % 4 == 0 (true for all call sites).
template <bool RELU>
__global__ __launch_bounds__(256)
void sgemm_bias(const float* __restrict__ A, const float* __restrict__ B,
                const float* __restrict__ bias, float* __restrict__ C,
                int M, int N, int K) {
    __shared__ float As[8][128];
    __shared__ float Bs[8][128];

    int tid = threadIdx.x;
    int tr = tid / 16;
    int tc = tid % 16;
    int row0 = blockIdx.y * 128;
    int col0 = blockIdx.x * 128;

    int arow = tid >> 1;
    int acol = (tid & 1) * 4;
    int brow = tid >> 5;
    int bcol = (tid & 31) * 4;

    float acc[8][8];
    #pragma unroll
    for (int i = 0; i < 8; i++)
        #pragma unroll
        for (int j = 0; j < 8; j++) acc[i][j] = 0.0f;

    for (int k0 = 0; k0 < K; k0 += 8) {
        float4 av = make_float4(0.f, 0.f, 0.f, 0.f);
        if (row0 + arow < M)
            av = *(const float4*)(A + (size_t)(row0 + arow) * K + k0 + acol);
        As[acol + 0][arow] = av.x;
        As[acol + 1][arow] = av.y;
        As[acol + 2][arow] = av.z;
        As[acol + 3][arow] = av.w;

        float4 bv = make_float4(0.f, 0.f, 0.f, 0.f);
        if (col0 + bcol < N)
            bv = *(const float4*)(B + (size_t)(k0 + brow) * N + col0 + bcol);
        *(float4*)&Bs[brow][bcol] = bv;

        __syncthreads();

        #pragma unroll
        for (int k = 0; k < 8; k++) {
            float ra[8], rb[8];
            #pragma unroll
            for (int i = 0; i < 8; i++) ra[i] = As[k][tr * 8 + i];
            #pragma unroll
            for (int j = 0; j < 8; j++) rb[j] = Bs[k][tc * 8 + j];
            #pragma unroll
            for (int i = 0; i < 8; i++)
                #pragma unroll
                for (int j = 0; j < 8; j++)
                    acc[i][j] += ra[i] * rb[j];
        }
        __syncthreads();
    }

    #pragma unroll
    for (int i = 0; i < 8; i++) {
        int row = row0 + tr * 8 + i;
        if (row >= M) continue;
        #pragma unroll
        for (int j = 0; j < 8; j++) {
            int col = col0 + tc * 8 + j;
            if (col < N) {
                float v = acc[i][j] + bias[col];
                if (RELU) v = fmaxf(v, 0.0f);
                C[(size_t)row * N + col] = v;
            }
        }
    }
}

// ------------------------- attention logits (per edge) -------------------------
__global__ __launch_bounds__(128)
void alpha_kernel(const float* __restrict__ xl, const float* __restrict__ xr,
                  const int* __restrict__ src, const int* __restrict__ dst,
                  const float* __restrict__ att, float* __restrict__ alpha, int ET) {
    int e = blockIdx.x;
    if (e >= ET) return;
    int s = src[e], d = dst[e];
    const float* pl = xl + (size_t)s * 4096;
    const float* pr = xr + (size_t)d * 4096;
    int t = threadIdx.x;

    float part[N_HEADS];
    #pragma unroll
    for (int h = 0; h < N_HEADS; h++) part[h] = 0.0f;

    #pragma unroll
    for (int h = 0; h < N_HEADS; h++) {
        const float* ah = att + h * OUTC;
        const float* lh = pl + h * OUTC;
        const float* rh = pr + h * OUTC;
        #pragma unroll
        for (int j = 0; j < OUTC / 128; j++) {
            int c = t + j * 128;
            float v = lh[c] + rh[c];
            v = (v > 0.0f) ? v : NSLOPE * v;
            part[h] += v * ah[c];
        }
    }

    __shared__ float red[4][N_HEADS];
    int lane = t & 31, wid = t >> 5;
    #pragma unroll
    for (int h = 0; h < N_HEADS; h++) {
        float v = part[h];
        #pragma unroll
        for (int o = 16; o; o >>= 1) v += __shfl_xor_sync(0xffffffffu, v, o);
        if (lane == 0) red[wid][h] = v;
    }
    __syncthreads();
    if (t < N_HEADS)
        alpha[(size_t)e * N_HEADS + t] =
            red[0][t] + red[1][t] + red[2][t] + red[3][t];
}

// ------------------------- per-node softmax over incoming edges ----------------
__global__ void softmax_kernel(const int* __restrict__ off, const int* __restrict__ csr,
                               float* __restrict__ alpha, int N) {
    int warp = (blockIdx.x * blockDim.x + threadIdx.x) >> 5;
    int lane = threadIdx.x & 31;
    if (warp >= N) return;
    int b = off[warp], e2 = off[warp + 1];
    #pragma unroll
    for (int h = 0; h < N_HEADS; h++) {
        float m = -1e30f;
        for (int i = b + lane; i < e2; i += 32)
            m = fmaxf(m, alpha[(size_t)csr[i] * N_HEADS + h]);
        #pragma unroll
        for (int o = 16; o; o >>= 1) m = fmaxf(m, __shfl_xor_sync(0xffffffffu, m, o));
        float z = 0.0f;
        for (int i = b + lane; i < e2; i += 32)
            z += expf(alpha[(size_t)csr[i] * N_HEADS + h] - m);
        #pragma unroll
        for (int o = 16; o; o >>= 1) z += __shfl_xor_sync(0xffffffffu, z, o);
        float inv = 1.0f / (z + 1e-16f);
        for (int i = b + lane; i < e2; i += 32) {
            size_t idx = (size_t)csr[i] * N_HEADS + h;
            alpha[idx] = expf(alpha[idx] - m) * inv;
        }
    }
}

// ------------------------- aggregation + head mean + bias ----------------------
__global__ __launch_bounds__(256)
void agg_kernel(const float* __restrict__ xl, const float* __restrict__ w,
                const int* __restrict__ off, const int* __restrict__ csr,
                const int* __restrict__ src, const float* __restrict__ gat_bias,
                float* __restrict__ outm, int N) {
    int n = blockIdx.x;
    if (n >= N) return;
    int t = threadIdx.x;
    int b = off[n], e2 = off[n + 1];

    float acc[4] = {0.f, 0.f, 0.f, 0.f};
    for (int i = b; i < e2; i++) {
        int e = csr[i];
        int s = src[e];
        const float* p = xl + (size_t)s * 4096;
        float w0 = w[(size_t)e * N_HEADS + 0];
        float w1 = w[(size_t)e * N_HEADS + 1];
        float w2 = w[(size_t)e * N_HEADS + 2];
        float w3 = w[(size_t)e * N_HEADS + 3];
        #pragma unroll
        for (int j = 0; j < 4; j++) {
            int c = t + j * 256;
            acc[j] += w0 * p[c] + w1 * p[1024 + c] + w2 * p[2048 + c] + w3 * p[3072 + c];
        }
    }
    #pragma unroll
    for (int j = 0; j < 4; j++) {
        int c = t + j * 256;
        outm[(size_t)n * 1024 + c] = acc[j] * 0.25f + gat_bias[c];
    }
}

// ------------------------- host orchestration -------------------------
static inline dim3 gemm_grid(int M, int N) {
    return dim3((N + 127) / 128, (M + 127) / 128);
}

extern "C" void kernel_launch(void* const* d_in, const int* in_sizes, int n_in,
                              void* d_out, int out_size) {
    const float* x    = (const float*)d_in[0];   // (Nx, 400) after flatten
    const float* emb  = (const float*)d_in[1];   // (Nc, 1024)
    const int*   ei   = (const int*)d_in[2];     // (E, 2) int32
    const float* exps = (const float*)d_in[3];   // (Nx, 460)
    const float* W1   = (const float*)d_in[4];
    const float* b1   = (const float*)d_in[5];
    const float* W2   = (const float*)d_in[6];
    const float* b2   = (const float*)d_in[7];
    const float* Wl   = (const float*)d_in[8];
    const float* bl   = (const float*)d_in[9];
    const float* Wr   = (const float*)d_in[10];
    const float* br   = (const float*)d_in[11];
    const float* att  = (const float*)d_in[12];
    const float* gb   = (const float*)d_in[13];
    const float* Wfc  = (const float*)d_in[14];
    const float* bfc  = (const float*)d_in[15];

    int Nx = in_sizes[0] / 400;
    int Nc = in_sizes[1] / 1024;
    int E  = in_sizes[2] / 2;
    int N  = Nx + Nc;
    int ET = E + N;

    float *xh, *xc, *xl, *xr, *outm, *alpha;
    int *src, *dst, *deg, *off, *cur, *csr;
    cudaGetSymbolAddress((void**)&xh,    g_xh);
    cudaGetSymbolAddress((void**)&xc,    g_xc);
    cudaGetSymbolAddress((void**)&xl,    g_xl);
    cudaGetSymbolAddress((void**)&xr,    g_xr);
    cudaGetSymbolAddress((void**)&outm,  g_outm);
    cudaGetSymbolAddress((void**)&alpha, g_alpha);
    cudaGetSymbolAddress((void**)&src,   g_src);
    cudaGetSymbolAddress((void**)&dst,   g_dst);
    cudaGetSymbolAddress((void**)&deg,   g_deg);
    cudaGetSymbolAddress((void**)&off,   g_off);
    cudaGetSymbolAddress((void**)&cur,   g_cur);
    cudaGetSymbolAddress((void**)&csr,   g_csr);

    // ---- graph structure ----
    zero_int2<<<(N + 255) / 256, 256>>>(deg, cur, N);
    build_edges<<<(ET + 255) / 256, 256>>>(ei, src, dst, deg, E, N);
    scan_excl<<<1, 1024>>>(deg, off, N);
    fill_csr<<<(ET + 255) / 256, 256>>>(dst, off, cur, csr, ET);

    // ---- MLP: xp = relu(xf @ W1 + b1) @ W2 + b2 ----
    sgemm_bias<true ><<<gemm_grid(Nx, 512), 256>>>(x,  W1, b1, xh, Nx, 512, 400);
    sgemm_bias<false><<<gemm_grid(Nx, 1024), 256>>>(xh, W2, b2, xc + (size_t)Nc * 1024, Nx, 1024, 512);

    // ---- concat: centroids at the front ----
    copy_f4<<<(Nc * 1024 / 4 + 255) / 256, 256>>>((const float4*)emb, (float4*)xc, Nc * 1024 / 4);

    // ---- projections xl, xr ----
    sgemm_bias<false><<<gemm_grid(N, 4096), 256>>>(xc, Wl, bl, xl, N, 4096, 1024);
    sgemm_bias<false><<<gemm_grid(N, 4096), 256>>>(xc, Wr, br, xr, N, 4096, 1024);

    // ---- GATv2 attention ----
    alpha_kernel<<<ET, 128>>>(xl, xr, src, dst, att, alpha, ET);
    softmax_kernel<<<(N * 32 + 255) / 256, 256>>>(off, csr, alpha, N);
    agg_kernel<<<N, 256>>>(xl, alpha, off, csr, src, gb, outm, N);

    // ---- final FC into d_out, then passthrough exps ----
    sgemm_bias<false><<<gemm_grid(N, 460), 256>>>(outm, Wfc, bfc, (float*)d_out, N, 460, 1024);
    copy_f4<<<(Nx * 460 / 4 + 255) / 256, 256>>>((const float4*)exps,
                                                 (float4*)((float*)d_out + (size_t)N * 460),
                                                 Nx * 460 / 4);
}

// round 3
// speedup vs baseline: 2.8468x; 2.8468x over previous
#include <cuda_runtime.h>
#include <cstdint>

#define N_HEADS 4
#define OUTC 1024
#define NSLOPE 0.2f

#define MAXNX 9000
#define MAXNC 1000
#define MAXN  (MAXNX + MAXNC)
#define MAXE0 40000
#define MAXE  (MAXE0 + MAXN)

// ------------------------- static scratch (no allocs) -------------------------
__device__ float g_xin[MAXNX * 400];           // tf32-rounded input x
__device__ float g_xh[MAXNX * 512];            // MLP hidden
__device__ float g_xc[MAXN * 1024];            // concat features
__device__ float g_xl[MAXN * 4096];            // left projection  (N, H*OUT)
__device__ float g_xr[MAXN * 4096];            // right projection
__device__ float g_outm[MAXN * 1024];          // head-mean aggregated output
__device__ float g_alpha[MAXE * N_HEADS];      // attention logits -> weights
__device__ float g_wbuf[1024 * 4096];          // tf32-rounded weight scratch
__device__ int   g_src[MAXE];
__device__ int   g_dst[MAXE];
__device__ int   g_deg[MAXN];
__device__ int   g_off[MAXN + 1];
__device__ int   g_cur[MAXN];
__device__ int   g_csr[MAXE];

// ------------------------- small utility kernels -------------------------
__global__ void zero_int2(int* a, int* b, int n) {
    int i = blockIdx.x * blockDim.x + threadIdx.x;
    if (i < n) { a[i] = 0; b[i] = 0; }
}

__global__ void copy_f4(const float4* __restrict__ src, float4* __restrict__ dst, int n4) {
    int i = blockIdx.x * blockDim.x + threadIdx.x;
    if (i < n4) dst[i] = src[i];
}

__device__ __forceinline__ float tf32r(float x) {
    uint32_t r;
    asm("cvt.rna.tf32.f32 %0, %1;" : "=r"(r) : "f"(x));
    return __uint_as_float(r);
}

__global__ void round_tf32_inplace(float* __restrict__ a, int n) {
    int i = blockIdx.x * blockDim.x + threadIdx.x;
    if (i < n) a[i] = tf32r(a[i]);
}

__global__ void round_tf32_copy(const float* __restrict__ a, float* __restrict__ b, int n) {
    int i = blockIdx.x * blockDim.x + threadIdx.x;
    if (i < n) b[i] = tf32r(a[i]);
}

// edge_index is int32 (JAX x64 disabled downcasts int64 -> int32)
__global__ void build_edges(const int* __restrict__ ei, int* __restrict__ src,
                            int* __restrict__ dst, int* __restrict__ deg, int E, int N) {
    int e = blockIdx.x * blockDim.x + threadIdx.x;
    int ET = E + N;
    if (e >= ET) return;
    int s, d;
    if (e < E) { s = ei[2 * e]; d = ei[2 * e + 1]; }
    else       { s = d = e - E; }
    src[e] = s;
    dst[e] = d;
    atomicAdd(&deg[d], 1);
}

__global__ void scan_excl(const int* __restrict__ deg, int* __restrict__ off, int n) {
    __shared__ int sh[1024];
    __shared__ int carry;
    if (threadIdx.x == 0) carry = 0;
    __syncthreads();
    for (int base = 0; base < n; base += 1024) {
        int i = base + threadIdx.x;
        int v = (i < n) ? deg[i] : 0;
        sh[threadIdx.x] = v;
        __syncthreads();
        #pragma unroll
        for (int ofs = 1; ofs < 1024; ofs <<= 1) {
            int t = (threadIdx.x >= ofs) ? sh[threadIdx.x - ofs] : 0;
            __syncthreads();
            sh[threadIdx.x] += t;
            __syncthreads();
        }
        if (i < n) off[i] = carry + sh[threadIdx.x] - v;
        __syncthreads();
        if (threadIdx.x == 1023) carry += sh[1023];
        __syncthreads();
    }
    if (threadIdx.x == 0) off[n] = carry;
}

__global__ void fill_csr(const int* __restrict__ dst, const int* __restrict__ off,
                         int* __restrict__ cur, int* __restrict__ csr, int ET) {
    int e = blockIdx.x * blockDim.x + threadIdx.x;
    if (e >= ET) return;
    int d = dst[e];
    int p = off[d] + atomicAdd(&cur[d], 1);
    csr[p] = e;
}

// ------------------------- tf32 tensor-core GEMM -------------------------
// C(MxN) = A(MxK) @ B(KxN) + bias, optional ReLU. A,B pre-rounded to tf32 bits.
// Block tile 128x256x32, 256 threads (8 warps of 64x64), cp.async double buffer.
#define BM 128
#define BN 256
#define BK 32
#define LDA 36            // 36 % 32 == 4 -> conflict-free A frag reads
#define LDB 260           // 260 % 32 == 4 -> conflict-free B frag reads
#define ASTAGE (BM * LDA) // floats
#define BSTAGE (BK * LDB)
#define SSTAGE (ASTAGE + BSTAGE)
#define GEMM_SMEM_BYTES (SSTAGE * 2 * 4)

__device__ __forceinline__ void cp16(uint32_t saddr, const float* g, bool valid) {
    int sz = valid ? 16 : 0;
    asm volatile("cp.async.cg.shared.global [%0], [%1], 16, %2;\n"
                 :: "r"(saddr), "l"(g), "r"(sz));
}

__device__ __forceinline__ void mma_tf32(float* c, const uint32_t* a, uint32_t b0, uint32_t b1) {
    asm volatile(
        "mma.sync.aligned.m16n8k8.row.col.f32.tf32.tf32.f32 "
        "{%0,%1,%2,%3}, {%4,%5,%6,%7}, {%8,%9}, {%0,%1,%2,%3};\n"
        : "+f"(c[0]), "+f"(c[1]), "+f"(c[2]), "+f"(c[3])
        : "r"(a[0]), "r"(a[1]), "r"(a[2]), "r"(a[3]), "r"(b0), "r"(b1));
}

template <bool RELU>
__global__ __launch_bounds__(256, 1)
void gemm_tf32(const float* __restrict__ A, const float* __restrict__ B,
               const float* __restrict__ bias, float* __restrict__ C,
               int M, int N, int K) {
    extern __shared__ float sm[];
    int tid  = threadIdx.x;
    int warp = tid >> 5;
    int lane = tid & 31;
    int g = lane >> 2;        // groupID 0..7
    int t = lane & 3;         // threadID_in_group 0..3
    int wm = warp >> 2;       // 0..1
    int wn = warp & 3;        // 0..3
    int mbase = wm * 64;
    int nbase = wn * 64;
    int am0 = blockIdx.y * BM;
    int bn0 = blockIdx.x * BN;
    int NIT = (K + BK - 1) / BK;

    float acc[4][8][4];
    #pragma unroll
    for (int i = 0; i < 4; i++)
        #pragma unroll
        for (int j = 0; j < 8; j++)
            #pragma unroll
            for (int k = 0; k < 4; k++) acc[i][j][k] = 0.0f;

    uint32_t smbase = (uint32_t)__cvta_generic_to_shared(sm);

    auto load_stage = [&](int it, int st) {
        int kt = it * BK;
        uint32_t as = smbase + (uint32_t)(st * SSTAGE) * 4u;
        uint32_t bs = as + (uint32_t)ASTAGE * 4u;
        // A: 128 rows x 8 float4
        #pragma unroll
        for (int i = 0; i < 4; i++) {
            int idx = tid + i * 256;
            int r  = idx >> 3;
            int c4 = (idx & 7) * 4;
            bool v = (am0 + r < M) && (kt + c4 + 4 <= K);
            const float* gp = A + (size_t)(v ? (am0 + r) : 0) * K + (v ? (kt + c4) : 0);
            cp16(as + (uint32_t)(r * LDA + c4) * 4u, gp, v);
        }
        // B: 32 rows x 64 float4
        #pragma unroll
        for (int i = 0; i < 8; i++) {
            int idx = tid + i * 256;
            int r  = idx >> 6;
            int c4 = (idx & 63) * 4;
            bool v = (kt + r < K) && (bn0 + c4 + 4 <= N);
            const float* gp = B + (size_t)(v ? (kt + r) : 0) * N + (v ? (bn0 + c4) : 0);
            cp16(bs + (uint32_t)(r * LDB + c4) * 4u, gp, v);
        }
        asm volatile("cp.async.commit_group;\n");
    };

    load_stage(0, 0);

    for (int it = 0; it < NIT; it++) {
        asm volatile("cp.async.wait_group 0;\n");
        __syncthreads();
        if (it + 1 < NIT) load_stage(it + 1, (it + 1) & 1);

        const float* As = sm + (it & 1) * SSTAGE;
        const float* Bs = As + ASTAGE;

        #pragma unroll
        for (int kk = 0; kk < BK; kk += 8) {
            uint32_t a[4][4];
            #pragma unroll
            for (int mf = 0; mf < 4; mf++) {
                int r = mbase + mf * 16 + g;
                a[mf][0] = __float_as_uint(As[r * LDA + kk + t]);
                a[mf][1] = __float_as_uint(As[(r + 8) * LDA + kk + t]);
                a[mf][2] = __float_as_uint(As[r * LDA + kk + t + 4]);
                a[mf][3] = __float_as_uint(As[(r + 8) * LDA + kk + t + 4]);
            }
            #pragma unroll
            for (int nf = 0; nf < 8; nf++) {
                int ccol = nbase + nf * 8 + g;
                uint32_t b0 = __float_as_uint(Bs[(kk + t) * LDB + ccol]);
                uint32_t b1 = __float_as_uint(Bs[(kk + t + 4) * LDB + ccol]);
                #pragma unroll
                for (int mf = 0; mf < 4; mf++)
                    mma_tf32(acc[mf][nf], a[mf], b0, b1);
            }
        }
        __syncthreads();
    }

    // epilogue: bias (+ReLU), float2 stores
    #pragma unroll
    for (int mf = 0; mf < 4; mf++) {
        int row0 = am0 + mbase + mf * 16 + g;
        int row1 = row0 + 8;
        #pragma unroll
        for (int nf = 0; nf < 8; nf++) {
            int col = bn0 + nbase + nf * 8 + 2 * t;
            if (col >= N) continue;
            float2 bv = *(const float2*)(bias + col);
            if (row0 < M) {
                float v0 = acc[mf][nf][0] + bv.x;
                float v1 = acc[mf][nf][1] + bv.y;
                if (RELU) { v0 = fmaxf(v0, 0.f); v1 = fmaxf(v1, 0.f); }
                *(float2*)(C + (size_t)row0 * N + col) = make_float2(v0, v1);
            }
            if (row1 < M) {
                float v2 = acc[mf][nf][2] + bv.x;
                float v3 = acc[mf][nf][3] + bv.y;
                if (RELU) { v2 = fmaxf(v2, 0.f); v3 = fmaxf(v3, 0.f); }
                *(float2*)(C + (size_t)row1 * N + col) = make_float2(v2, v3);
            }
        }
    }
}

// ------------------------- attention logits (per edge) -------------------------
__global__ __launch_bounds__(128)
void alpha_kernel(const float* __restrict__ xl, const float* __restrict__ xr,
                  const int* __restrict__ src, const int* __restrict__ dst,
                  const float* __restrict__ att, float* __restrict__ alpha, int ET) {
    int e = blockIdx.x;
    if (e >= ET) return;
    int s = src[e], d = dst[e];
    const float* pl = xl + (size_t)s * 4096;
    const float* pr = xr + (size_t)d * 4096;
    int t = threadIdx.x;

    float part[N_HEADS];
    #pragma unroll
    for (int h = 0; h < N_HEADS; h++) part[h] = 0.0f;

    #pragma unroll
    for (int h = 0; h < N_HEADS; h++) {
        const float* ah = att + h * OUTC;
        const float* lh = pl + h * OUTC;
        const float* rh = pr + h * OUTC;
        #pragma unroll
        for (int j = 0; j < OUTC / 128; j++) {
            int c = t + j * 128;
            float v = lh[c] + rh[c];
            v = (v > 0.0f) ? v : NSLOPE * v;
            part[h] += v * ah[c];
        }
    }

    __shared__ float red[4][N_HEADS];
    int lane = t & 31, wid = t >> 5;
    #pragma unroll
    for (int h = 0; h < N_HEADS; h++) {
        float v = part[h];
        #pragma unroll
        for (int o = 16; o; o >>= 1) v += __shfl_xor_sync(0xffffffffu, v, o);
        if (lane == 0) red[wid][h] = v;
    }
    __syncthreads();
    if (t < N_HEADS)
        alpha[(size_t)e * N_HEADS + t] =
            red[0][t] + red[1][t] + red[2][t] + red[3][t];
}

// ------------------------- per-node softmax over incoming edges ----------------
__global__ void softmax_kernel(const int* __restrict__ off, const int* __restrict__ csr,
                               float* __restrict__ alpha, int N) {
    int warp = (blockIdx.x * blockDim.x + threadIdx.x) >> 5;
    int lane = threadIdx.x & 31;
    if (warp >= N) return;
    int b = off[warp], e2 = off[warp + 1];
    #pragma unroll
    for (int h = 0; h < N_HEADS; h++) {
        float m = -1e30f;
        for (int i = b + lane; i < e2; i += 32)
            m = fmaxf(m, alpha[(size_t)csr[i] * N_HEADS + h]);
        #pragma unroll
        for (int o = 16; o; o >>= 1) m = fmaxf(m, __shfl_xor_sync(0xffffffffu, m, o));
        float z = 0.0f;
        for (int i = b + lane; i < e2; i += 32)
            z += expf(alpha[(size_t)csr[i] * N_HEADS + h] - m);
        #pragma unroll
        for (int o = 16; o; o >>= 1) z += __shfl_xor_sync(0xffffffffu, z, o);
        float inv = 1.0f / (z + 1e-16f);
        for (int i = b + lane; i < e2; i += 32) {
            size_t idx = (size_t)csr[i] * N_HEADS + h;
            alpha[idx] = expf(alpha[idx] - m) * inv;
        }
    }
}

// ------------------------- aggregation + head mean + bias ----------------------
__global__ __launch_bounds__(256)
void agg_kernel(const float* __restrict__ xl, const float* __restrict__ w,
                const int* __restrict__ off, const int* __restrict__ csr,
                const int* __restrict__ src, const float* __restrict__ gat_bias,
                float* __restrict__ outm, int N) {
    int n = blockIdx.x;
    if (n >= N) return;
    int t = threadIdx.x;
    int b = off[n], e2 = off[n + 1];

    float acc[4] = {0.f, 0.f, 0.f, 0.f};
    for (int i = b; i < e2; i++) {
        int e = csr[i];
        int s = src[e];
        const float* p = xl + (size_t)s * 4096;
        float w0 = w[(size_t)e * N_HEADS + 0];
        float w1 = w[(size_t)e * N_HEADS + 1];
        float w2 = w[(size_t)e * N_HEADS + 2];
        float w3 = w[(size_t)e * N_HEADS + 3];
        #pragma unroll
        for (int j = 0; j < 4; j++) {
            int c = t + j * 256;
            acc[j] += w0 * p[c] + w1 * p[1024 + c] + w2 * p[2048 + c] + w3 * p[3072 + c];
        }
    }
    #pragma unroll
    for (int j = 0; j < 4; j++) {
        int c = t + j * 256;
        outm[(size_t)n * 1024 + c] = acc[j] * 0.25f + gat_bias[c];
    }
}

// ------------------------- host orchestration -------------------------
static inline dim3 gemm_grid(int M, int N) {
    return dim3((N + BN - 1) / BN, (M + BM - 1) / BM);
}

extern "C" void kernel_launch(void* const* d_in, const int* in_sizes, int n_in,
                              void* d_out, int out_size) {
    const float* x    = (const float*)d_in[0];   // (Nx, 400)
    const float* emb  = (const float*)d_in[1];   // (Nc, 1024)
    const int*   ei   = (const int*)d_in[2];     // (E, 2) int32
    const float* exps = (const float*)d_in[3];   // (Nx, 460)
    const float* W1   = (const float*)d_in[4];
    const float* b1   = (const float*)d_in[5];
    const float* W2   = (const float*)d_in[6];
    const float* b2   = (const float*)d_in[7];
    const float* Wl   = (const float*)d_in[8];
    const float* bl   = (const float*)d_in[9];
    const float* Wr   = (const float*)d_in[10];
    const float* br   = (const float*)d_in[11];
    const float* att  = (const float*)d_in[12];
    const float* gb   = (const float*)d_in[13];
    const float* Wfc  = (const float*)d_in[14];
    const float* bfc  = (const float*)d_in[15];

    int Nx = in_sizes[0] / 400;
    int Nc = in_sizes[1] / 1024;
    int E  = in_sizes[2] / 2;
    int N  = Nx + Nc;
    int ET = E + N;

    float *xin, *xh, *xc, *xl, *xr, *outm, *alpha, *wbuf;
    int *src, *dst, *deg, *off, *cur, *csr;
    cudaGetSymbolAddress((void**)&xin,   g_xin);
    cudaGetSymbolAddress((void**)&xh,    g_xh);
    cudaGetSymbolAddress((void**)&xc,    g_xc);
    cudaGetSymbolAddress((void**)&xl,    g_xl);
    cudaGetSymbolAddress((void**)&xr,    g_xr);
    cudaGetSymbolAddress((void**)&outm,  g_outm);
    cudaGetSymbolAddress((void**)&alpha, g_alpha);
    cudaGetSymbolAddress((void**)&wbuf,  g_wbuf);
    cudaGetSymbolAddress((void**)&src,   g_src);
    cudaGetSymbolAddress((void**)&dst,   g_dst);
    cudaGetSymbolAddress((void**)&deg,   g_deg);
    cudaGetSymbolAddress((void**)&off,   g_off);
    cudaGetSymbolAddress((void**)&cur,   g_cur);
    cudaGetSymbolAddress((void**)&csr,   g_csr);

    cudaFuncSetAttribute(gemm_tf32<true>,  cudaFuncAttributeMaxDynamicSharedMemorySize, GEMM_SMEM_BYTES);
    cudaFuncSetAttribute(gemm_tf32<false>, cudaFuncAttributeMaxDynamicSharedMemorySize, GEMM_SMEM_BYTES);

    // ---- graph structure ----
    zero_int2<<<(N + 255) / 256, 256>>>(deg, cur, N);
    build_edges<<<(ET + 255) / 256, 256>>>(ei, src, dst, deg, E, N);
    scan_excl<<<1, 1024>>>(deg, off, N);
    fill_csr<<<(ET + 255) / 256, 256>>>(dst, off, cur, csr, ET);

    // ---- MLP: xp = relu(xf @ W1 + b1) @ W2 + b2 (tf32) ----
    round_tf32_copy<<<(Nx * 400 + 255) / 256, 256>>>(x, xin, Nx * 400);
    round_tf32_copy<<<(400 * 512 + 255) / 256, 256>>>(W1, wbuf, 400 * 512);
    gemm_tf32<true><<<gemm_grid(Nx, 512), 256, GEMM_SMEM_BYTES>>>(xin, wbuf, b1, xh, Nx, 512, 400);

    round_tf32_inplace<<<(Nx * 512 + 255) / 256, 256>>>(xh, Nx * 512);
    round_tf32_copy<<<(512 * 1024 + 255) / 256, 256>>>(W2, wbuf, 512 * 1024);
    gemm_tf32<false><<<gemm_grid(Nx, 1024), 256, GEMM_SMEM_BYTES>>>(xh, wbuf, b2, xc + (size_t)Nc * 1024, Nx, 1024, 512);

    // ---- concat: centroids at the front, then round xc to tf32 ----
    copy_f4<<<(Nc * 1024 / 4 + 255) / 256, 256>>>((const float4*)emb, (float4*)xc, Nc * 1024 / 4);
    round_tf32_inplace<<<(N * 1024 + 255) / 256, 256>>>(xc, N * 1024);

    // ---- projections xl, xr (tf32) ----
    round_tf32_copy<<<(1024 * 4096 + 255) / 256, 256>>>(Wl, wbuf, 1024 * 4096);
    gemm_tf32<false><<<gemm_grid(N, 4096), 256, GEMM_SMEM_BYTES>>>(xc, wbuf, bl, xl, N, 4096, 1024);
    round_tf32_copy<<<(1024 * 4096 + 255) / 256, 256>>>(Wr, wbuf, 1024 * 4096);
    gemm_tf32<false><<<gemm_grid(N, 4096), 256, GEMM_SMEM_BYTES>>>(xc, wbuf, br, xr, N, 4096, 1024);

    // ---- GATv2 attention (fp32) ----
    alpha_kernel<<<ET, 128>>>(xl, xr, src, dst, att, alpha, ET);
    softmax_kernel<<<(N * 32 + 255) / 256, 256>>>(off, csr, alpha, N);
    agg_kernel<<<N, 256>>>(xl, alpha, off, csr, src, gb, outm, N);

    // ---- final FC into d_out (tf32), then passthrough exps ----
    round_tf32_inplace<<<(N * 1024 + 255) / 256, 256>>>(outm, N * 1024);
    round_tf32_copy<<<(1024 * 460 + 255) / 256, 256>>>(Wfc, wbuf, 1024 * 460);
    gemm_tf32<false><<<gemm_grid(N, 460), 256, GEMM_SMEM_BYTES>>>(outm, wbuf, bfc, (float*)d_out, N, 460, 1024);

    copy_f4<<<(Nx * 460 / 4 + 255) / 256, 256>>>((const float4*)exps,
                                                 (float4*)((float*)d_out + (size_t)N * 460),
                                                 Nx * 460 / 4);
}

// round 4
// speedup vs baseline: 2.9850x; 1.0485x over previous
#include <cuda_runtime.h>
#include <cstdint>

#define N_HEADS 4
#define OUTC 1024
#define NSLOPE 0.2f

#define MAXNX 9000
#define MAXNC 1000
#define MAXN  (MAXNX + MAXNC)
#define MAXE0 40000
#define MAXE  (MAXE0 + MAXN)

// ------------------------- static scratch (no allocs) -------------------------
__device__ float g_xin[MAXNX * 400];           // tf32-rounded input x
__device__ float g_xh[MAXNX * 512];            // MLP hidden
__device__ float g_xc[MAXN * 1024];            // concat features
__device__ float g_xl[MAXN * 4096];            // left projection  (N, H*OUT)
__device__ float g_xr[MAXN * 4096];            // right projection
__device__ float g_outm[MAXN * 1024];          // head-mean aggregated output
__device__ float g_alpha[MAXE * N_HEADS];      // attention logits scratch (csr order)
__device__ float g_wbuf[1024 * 4096];          // tf32-rounded weight scratch
__device__ int   g_src[MAXE];
__device__ int   g_dst[MAXE];
__device__ int   g_deg[MAXN];
__device__ int   g_off[MAXN + 1];
__device__ int   g_cur[MAXN];
__device__ int   g_csr[MAXE];

// ------------------------- small utility kernels -------------------------
__global__ void zero_int2(int* a, int* b, int n) {
    int i = blockIdx.x * blockDim.x + threadIdx.x;
    if (i < n) { a[i] = 0; b[i] = 0; }
}

__global__ void copy_f4(const float4* __restrict__ src, float4* __restrict__ dst, int n4) {
    int i = blockIdx.x * blockDim.x + threadIdx.x;
    if (i < n4) dst[i] = src[i];
}

__device__ __forceinline__ float tf32r(float x) {
    uint32_t r;
    asm("cvt.rna.tf32.f32 %0, %1;" : "=r"(r) : "f"(x));
    return __uint_as_float(r);
}

__global__ void round_tf32_inplace(float* __restrict__ a, int n) {
    int i = blockIdx.x * blockDim.x + threadIdx.x;
    if (i < n) a[i] = tf32r(a[i]);
}

__global__ void round_tf32_copy(const float* __restrict__ a, float* __restrict__ b, int n) {
    int i = blockIdx.x * blockDim.x + threadIdx.x;
    if (i < n) b[i] = tf32r(a[i]);
}

// edge_index is int32 (JAX x64 disabled downcasts int64 -> int32)
__global__ void build_edges(const int* __restrict__ ei, int* __restrict__ src,
                            int* __restrict__ dst, int* __restrict__ deg, int E, int N) {
    int e = blockIdx.x * blockDim.x + threadIdx.x;
    int ET = E + N;
    if (e >= ET) return;
    int s, d;
    if (e < E) { s = ei[2 * e]; d = ei[2 * e + 1]; }
    else       { s = d = e - E; }
    src[e] = s;
    dst[e] = d;
    atomicAdd(&deg[d], 1);
}

__global__ void scan_excl(const int* __restrict__ deg, int* __restrict__ off, int n) {
    __shared__ int sh[1024];
    __shared__ int carry;
    if (threadIdx.x == 0) carry = 0;
    __syncthreads();
    for (int base = 0; base < n; base += 1024) {
        int i = base + threadIdx.x;
        int v = (i < n) ? deg[i] : 0;
        sh[threadIdx.x] = v;
        __syncthreads();
        #pragma unroll
        for (int ofs = 1; ofs < 1024; ofs <<= 1) {
            int t = (threadIdx.x >= ofs) ? sh[threadIdx.x - ofs] : 0;
            __syncthreads();
            sh[threadIdx.x] += t;
            __syncthreads();
        }
        if (i < n) off[i] = carry + sh[threadIdx.x] - v;
        __syncthreads();
        if (threadIdx.x == 1023) carry += sh[1023];
        __syncthreads();
    }
    if (threadIdx.x == 0) off[n] = carry;
}

__global__ void fill_csr(const int* __restrict__ dst, const int* __restrict__ off,
                         int* __restrict__ cur, int* __restrict__ csr, int ET) {
    int e = blockIdx.x * blockDim.x + threadIdx.x;
    if (e >= ET) return;
    int d = dst[e];
    int p = off[d] + atomicAdd(&cur[d], 1);
    csr[p] = e;
}

// ------------------------- tf32 tensor-core GEMM -------------------------
// C(MxN) = A(MxK) @ B(KxN) + bias, optional ReLU. A,B pre-rounded to tf32 bits.
// Block tile 128x256x32, 256 threads (8 warps of 64x64), cp.async 3-stage buffer.
#define BM 128
#define BN 256
#define BK 32
#define LDA 36            // 36 % 32 == 4 -> conflict-free A frag reads
#define LDB 260           // 260 % 32 == 4 -> conflict-free B frag reads
#define ASTAGE (BM * LDA) // floats
#define BSTAGE (BK * LDB)
#define SSTAGE (ASTAGE + BSTAGE)
#define NSTAGES 3
#define GEMM_SMEM_BYTES (SSTAGE * NSTAGES * 4)

__device__ __forceinline__ void cp16(uint32_t saddr, const float* g, bool valid) {
    int sz = valid ? 16 : 0;
    asm volatile("cp.async.cg.shared.global [%0], [%1], 16, %2;\n"
                 :: "r"(saddr), "l"(g), "r"(sz));
}

__device__ __forceinline__ void mma_tf32(float* c, const uint32_t* a, uint32_t b0, uint32_t b1) {
    asm volatile(
        "mma.sync.aligned.m16n8k8.row.col.f32.tf32.tf32.f32 "
        "{%0,%1,%2,%3}, {%4,%5,%6,%7}, {%8,%9}, {%0,%1,%2,%3};\n"
        : "+f"(c[0]), "+f"(c[1]), "+f"(c[2]), "+f"(c[3])
        : "r"(a[0]), "r"(a[1]), "r"(a[2]), "r"(a[3]), "r"(b0), "r"(b1));
}

template <bool RELU>
__global__ __launch_bounds__(256, 1)
void gemm_tf32(const float* __restrict__ A, const float* __restrict__ B,
               const float* __restrict__ bias, float* __restrict__ C,
               int M, int N, int K) {
    extern __shared__ float sm[];
    int tid  = threadIdx.x;
    int warp = tid >> 5;
    int lane = tid & 31;
    int g = lane >> 2;
    int t = lane & 3;
    int wm = warp >> 2;
    int wn = warp & 3;
    int mbase = wm * 64;
    int nbase = wn * 64;
    int am0 = blockIdx.y * BM;
    int bn0 = blockIdx.x * BN;
    int NIT = (K + BK - 1) / BK;

    float acc[4][8][4];
    #pragma unroll
    for (int i = 0; i < 4; i++)
        #pragma unroll
        for (int j = 0; j < 8; j++)
            #pragma unroll
            for (int k = 0; k < 4; k++) acc[i][j][k] = 0.0f;

    uint32_t smbase = (uint32_t)__cvta_generic_to_shared(sm);

    auto load_stage = [&](int it, int st) {
        int kt = it * BK;
        uint32_t as = smbase + (uint32_t)(st * SSTAGE) * 4u;
        uint32_t bs = as + (uint32_t)ASTAGE * 4u;
        #pragma unroll
        for (int i = 0; i < 4; i++) {
            int idx = tid + i * 256;
            int r  = idx >> 3;
            int c4 = (idx & 7) * 4;
            bool v = (am0 + r < M) && (kt + c4 + 4 <= K);
            const float* gp = A + (size_t)(v ? (am0 + r) : 0) * K + (v ? (kt + c4) : 0);
            cp16(as + (uint32_t)(r * LDA + c4) * 4u, gp, v);
        }
        #pragma unroll
        for (int i = 0; i < 8; i++) {
            int idx = tid + i * 256;
            int r  = idx >> 6;
            int c4 = (idx & 63) * 4;
            bool v = (kt + r < K) && (bn0 + c4 + 4 <= N);
            const float* gp = B + (size_t)(v ? (kt + r) : 0) * N + (v ? (bn0 + c4) : 0);
            cp16(bs + (uint32_t)(r * LDB + c4) * 4u, gp, v);
        }
        asm volatile("cp.async.commit_group;\n");
    };

    load_stage(0, 0);
    if (NIT > 1) load_stage(1, 1);

    for (int it = 0; it < NIT; it++) {
        asm volatile("cp.async.wait_group 1;\n");
        __syncthreads();
        if (it + 2 < NIT) load_stage(it + 2, (it + 2) % NSTAGES);

        const float* As = sm + (it % NSTAGES) * SSTAGE;
        const float* Bs = As + ASTAGE;

        #pragma unroll
        for (int kk = 0; kk < BK; kk += 8) {
            uint32_t a[4][4];
            #pragma unroll
            for (int mf = 0; mf < 4; mf++) {
                int r = mbase + mf * 16 + g;
                a[mf][0] = __float_as_uint(As[r * LDA + kk + t]);
                a[mf][1] = __float_as_uint(As[(r + 8) * LDA + kk + t]);
                a[mf][2] = __float_as_uint(As[r * LDA + kk + t + 4]);
                a[mf][3] = __float_as_uint(As[(r + 8) * LDA + kk + t + 4]);
            }
            #pragma unroll
            for (int nf = 0; nf < 8; nf++) {
                int ccol = nbase + nf * 8 + g;
                uint32_t b0 = __float_as_uint(Bs[(kk + t) * LDB + ccol]);
                uint32_t b1 = __float_as_uint(Bs[(kk + t + 4) * LDB + ccol]);
                #pragma unroll
                for (int mf = 0; mf < 4; mf++)
                    mma_tf32(acc[mf][nf], a[mf], b0, b1);
            }
        }
        __syncthreads();
    }

    #pragma unroll
    for (int mf = 0; mf < 4; mf++) {
        int row0 = am0 + mbase + mf * 16 + g;
        int row1 = row0 + 8;
        #pragma unroll
        for (int nf = 0; nf < 8; nf++) {
            int col = bn0 + nbase + nf * 8 + 2 * t;
            if (col >= N) continue;
            float2 bv = *(const float2*)(bias + col);
            if (row0 < M) {
                float v0 = acc[mf][nf][0] + bv.x;
                float v1 = acc[mf][nf][1] + bv.y;
                if (RELU) { v0 = fmaxf(v0, 0.f); v1 = fmaxf(v1, 0.f); }
                *(float2*)(C + (size_t)row0 * N + col) = make_float2(v0, v1);
            }
            if (row1 < M) {
                float v2 = acc[mf][nf][2] + bv.x;
                float v3 = acc[mf][nf][3] + bv.y;
                if (RELU) { v2 = fmaxf(v2, 0.f); v3 = fmaxf(v3, 0.f); }
                *(float2*)(C + (size_t)row1 * N + col) = make_float2(v2, v3);
            }
        }
    }
}

// ------------------------- fused GATv2: alpha + softmax + aggregate ------------
// One block per dst node (CSR order). xr[dst] and att stay in registers for all
// of the node's incoming edges; online softmax (m,z); second pass re-reads
// xl[src] rows (L2-hot) for the weighted sum; head-mean + bias fused.
__global__ __launch_bounds__(256)
void gat_fused(const float* __restrict__ xl, const float* __restrict__ xr,
               const int* __restrict__ off, const int* __restrict__ csr,
               const int* __restrict__ src, const float* __restrict__ att,
               const float* __restrict__ gat_bias, float* __restrict__ alpha_s,
               float* __restrict__ outm, int N) {
    int n = blockIdx.x;
    if (n >= N) return;
    int t = threadIdx.x;
    int lane = t & 31, wid = t >> 5;
    int b = off[n], e2 = off[n + 1];

    float xrreg[16], attreg[16];
    const float* xrp = xr + (size_t)n * 4096;
    #pragma unroll
    for (int j = 0; j < 16; j++) {
        xrreg[j]  = xrp[t + j * 256];
        attreg[j] = att[t + j * 256];   // flat (H*OUT) matches h*1024+c layout
    }

    __shared__ float warpred[8][N_HEADS];
    __shared__ float sm_m[N_HEADS], sm_z[N_HEADS];
    __shared__ float sm_w[N_HEADS];
    if (t < N_HEADS) { sm_m[t] = -1e30f; sm_z[t] = 0.0f; }
    __syncthreads();

    // ---- pass 1: logits + online softmax stats ----
    for (int i = b; i < e2; i++) {
        int e = csr[i];
        int s = src[e];
        const float* pl = xl + (size_t)s * 4096;
        float part[N_HEADS] = {0.f, 0.f, 0.f, 0.f};
        #pragma unroll
        for (int j = 0; j < 16; j++) {
            float v = pl[t + j * 256] + xrreg[j];
            v = (v > 0.0f) ? v : NSLOPE * v;
            part[j >> 2] += v * attreg[j];
        }
        #pragma unroll
        for (int h = 0; h < N_HEADS; h++) {
            float v = part[h];
            #pragma unroll
            for (int o = 16; o; o >>= 1) v += __shfl_xor_sync(0xffffffffu, v, o);
            if (lane == 0) warpred[wid][h] = v;
        }
        __syncthreads();
        if (t < N_HEADS) {
            float a = 0.f;
            #pragma unroll
            for (int w = 0; w < 8; w++) a += warpred[w][t];
            alpha_s[(size_t)i * N_HEADS + t] = a;
            float m = sm_m[t], z = sm_z[t];
            if (a > m) { z = z * __expf(m - a) + 1.0f; m = a; }
            else       { z += __expf(a - m); }
            sm_m[t] = m; sm_z[t] = z;
        }
        __syncthreads();
    }

    if (t < N_HEADS) sm_w[t] = 1.0f / (sm_z[t] + 1e-16f);
    __syncthreads();
    float mf0 = sm_m[0], mf1 = sm_m[1], mf2 = sm_m[2], mf3 = sm_m[3];
    float iv0 = sm_w[0], iv1 = sm_w[1], iv2 = sm_w[2], iv3 = sm_w[3];

    // ---- pass 2: weighted aggregation ----
    float acc[16];
    #pragma unroll
    for (int j = 0; j < 16; j++) acc[j] = 0.0f;

    for (int i = b; i < e2; i++) {
        int e = csr[i];
        int s = src[e];
        const float* pl = xl + (size_t)s * 4096;
        const float* ap = alpha_s + (size_t)i * N_HEADS;
        float w[N_HEADS];
        w[0] = __expf(ap[0] - mf0) * iv0;
        w[1] = __expf(ap[1] - mf1) * iv1;
        w[2] = __expf(ap[2] - mf2) * iv2;
        w[3] = __expf(ap[3] - mf3) * iv3;
        #pragma unroll
        for (int j = 0; j < 16; j++)
            acc[j] += w[j >> 2] * pl[t + j * 256];
    }

    // head mean + bias: channel c gets heads at j, j+4, j+8, j+12
    #pragma unroll
    for (int jc = 0; jc < 4; jc++) {
        int c = t + jc * 256;
        float v = 0.25f * (acc[jc] + acc[jc + 4] + acc[jc + 8] + acc[jc + 12]);
        outm[(size_t)n * 1024 + c] = v + gat_bias[c];
    }
}

// ------------------------- host orchestration -------------------------
static inline dim3 gemm_grid(int M, int N) {
    return dim3((N + BN - 1) / BN, (M + BM - 1) / BM);
}

extern "C" void kernel_launch(void* const* d_in, const int* in_sizes, int n_in,
                              void* d_out, int out_size) {
    const float* x    = (const float*)d_in[0];
    const float* emb  = (const float*)d_in[1];
    const int*   ei   = (const int*)d_in[2];
    const float* exps = (const float*)d_in[3];
    const float* W1   = (const float*)d_in[4];
    const float* b1   = (const float*)d_in[5];
    const float* W2   = (const float*)d_in[6];
    const float* b2   = (const float*)d_in[7];
    const float* Wl   = (const float*)d_in[8];
    const float* bl   = (const float*)d_in[9];
    const float* Wr   = (const float*)d_in[10];
    const float* br   = (const float*)d_in[11];
    const float* att  = (const float*)d_in[12];
    const float* gb   = (const float*)d_in[13];
    const float* Wfc  = (const float*)d_in[14];
    const float* bfc  = (const float*)d_in[15];

    int Nx = in_sizes[0] / 400;
    int Nc = in_sizes[1] / 1024;
    int E  = in_sizes[2] / 2;
    int N  = Nx + Nc;
    int ET = E + N;

    float *xin, *xh, *xc, *xl, *xr, *outm, *alpha, *wbuf;
    int *src, *dst, *deg, *off, *cur, *csr;
    cudaGetSymbolAddress((void**)&xin,   g_xin);
    cudaGetSymbolAddress((void**)&xh,    g_xh);
    cudaGetSymbolAddress((void**)&xc,    g_xc);
    cudaGetSymbolAddress((void**)&xl,    g_xl);
    cudaGetSymbolAddress((void**)&xr,    g_xr);
    cudaGetSymbolAddress((void**)&outm,  g_outm);
    cudaGetSymbolAddress((void**)&alpha, g_alpha);
    cudaGetSymbolAddress((void**)&wbuf,  g_wbuf);
    cudaGetSymbolAddress((void**)&src,   g_src);
    cudaGetSymbolAddress((void**)&dst,   g_dst);
    cudaGetSymbolAddress((void**)&deg,   g_deg);
    cudaGetSymbolAddress((void**)&off,   g_off);
    cudaGetSymbolAddress((void**)&cur,   g_cur);
    cudaGetSymbolAddress((void**)&csr,   g_csr);

    cudaFuncSetAttribute(gemm_tf32<true>,  cudaFuncAttributeMaxDynamicSharedMemorySize, GEMM_SMEM_BYTES);
    cudaFuncSetAttribute(gemm_tf32<false>, cudaFuncAttributeMaxDynamicSharedMemorySize, GEMM_SMEM_BYTES);

    // ---- graph structure ----
    zero_int2<<<(N + 255) / 256, 256>>>(deg, cur, N);
    build_edges<<<(ET + 255) / 256, 256>>>(ei, src, dst, deg, E, N);
    scan_excl<<<1, 1024>>>(deg, off, N);
    fill_csr<<<(ET + 255) / 256, 256>>>(dst, off, cur, csr, ET);

    // ---- MLP: xp = relu(xf @ W1 + b1) @ W2 + b2 (tf32) ----
    round_tf32_copy<<<(Nx * 400 + 255) / 256, 256>>>(x, xin, Nx * 400);
    round_tf32_copy<<<(400 * 512 + 255) / 256, 256>>>(W1, wbuf, 400 * 512);
    gemm_tf32<true><<<gemm_grid(Nx, 512), 256, GEMM_SMEM_BYTES>>>(xin, wbuf, b1, xh, Nx, 512, 400);

    round_tf32_inplace<<<(Nx * 512 + 255) / 256, 256>>>(xh, Nx * 512);
    round_tf32_copy<<<(512 * 1024 + 255) / 256, 256>>>(W2, wbuf, 512 * 1024);
    gemm_tf32<false><<<gemm_grid(Nx, 1024), 256, GEMM_SMEM_BYTES>>>(xh, wbuf, b2, xc + (size_t)Nc * 1024, Nx, 1024, 512);

    // ---- concat: centroids at the front, then round xc to tf32 ----
    copy_f4<<<(Nc * 1024 / 4 + 255) / 256, 256>>>((const float4*)emb, (float4*)xc, Nc * 1024 / 4);
    round_tf32_inplace<<<(N * 1024 + 255) / 256, 256>>>(xc, N * 1024);

    // ---- projections xl, xr (tf32) ----
    round_tf32_copy<<<(1024 * 4096 + 255) / 256, 256>>>(Wl, wbuf, 1024 * 4096);
    gemm_tf32<false><<<gemm_grid(N, 4096), 256, GEMM_SMEM_BYTES>>>(xc, wbuf, bl, xl, N, 4096, 1024);
    round_tf32_copy<<<(1024 * 4096 + 255) / 256, 256>>>(Wr, wbuf, 1024 * 4096);
    gemm_tf32<false><<<gemm_grid(N, 4096), 256, GEMM_SMEM_BYTES>>>(xc, wbuf, br, xr, N, 4096, 1024);

    // ---- fused GATv2 attention + softmax + aggregation ----
    gat_fused<<<N, 256>>>(xl, xr, off, csr, src, att, gb, alpha, outm, N);

    // ---- final FC into d_out (tf32), then passthrough exps ----
    round_tf32_inplace<<<(N * 1024 + 255) / 256, 256>>>(outm, N * 1024);
    round_tf32_copy<<<(1024 * 460 + 255) / 256, 256>>>(Wfc, wbuf, 1024 * 460);
    gemm_tf32<false><<<gemm_grid(N, 460), 256, GEMM_SMEM_BYTES>>>(outm, wbuf, bfc, (float*)d_out, N, 460, 1024);

    copy_f4<<<(Nx * 460 / 4 + 255) / 256, 256>>>((const float4*)exps,
                                                 (float4*)((float*)d_out + (size_t)N * 460),
                                                 Nx * 460 / 4);
}

// round 5
// speedup vs baseline: 2.9915x; 1.0022x over previous
#include <cuda_runtime.h>
#include <cstdint>

#define N_HEADS 4
#define OUTC 1024
#define NSLOPE 0.2f

#define MAXNX 9000
#define MAXNC 1000
#define MAXN  (MAXNX + MAXNC)
#define MAXE0 40000
#define MAXE  (MAXE0 + MAXN)

// ------------------------- static scratch (no allocs) -------------------------
__device__ float g_xin[MAXNX * 400];
__device__ float g_xh[MAXNX * 512];
__device__ float g_xc[MAXN * 1024];
__device__ float g_xl[MAXN * 4096];
__device__ float g_xr[MAXN * 4096];
__device__ float g_outm[MAXN * 1024];
__device__ float g_alpha[MAXE * N_HEADS];
__device__ float g_wbuf[1024 * 4096];
__device__ int   g_src[MAXE];
__device__ int   g_dst[MAXE];
__device__ int   g_deg[MAXN];
__device__ int   g_off[MAXN + 1];
__device__ int   g_cur[MAXN];
__device__ int   g_csr[MAXE];

// ------------------------- small utility kernels -------------------------
__global__ void zero_int2(int* a, int* b, int n) {
    int i = blockIdx.x * blockDim.x + threadIdx.x;
    if (i < n) { a[i] = 0; b[i] = 0; }
}

__global__ void copy_f4(const float4* __restrict__ src, float4* __restrict__ dst, int n4) {
    int i = blockIdx.x * blockDim.x + threadIdx.x;
    if (i < n4) dst[i] = src[i];
}

__device__ __forceinline__ float tf32r(float x) {
    uint32_t r;
    asm("cvt.rna.tf32.f32 %0, %1;" : "=r"(r) : "f"(x));
    return __uint_as_float(r);
}

// vectorized tf32 rounding (n must be divisible by 4 — true for all call sites)
__global__ void round_tf32_inplace4(float4* __restrict__ a, int n4) {
    int i = blockIdx.x * blockDim.x + threadIdx.x;
    if (i < n4) {
        float4 v = a[i];
        v.x = tf32r(v.x); v.y = tf32r(v.y); v.z = tf32r(v.z); v.w = tf32r(v.w);
        a[i] = v;
    }
}

__global__ void round_tf32_copy4(const float4* __restrict__ a, float4* __restrict__ b, int n4) {
    int i = blockIdx.x * blockDim.x + threadIdx.x;
    if (i < n4) {
        float4 v = a[i];
        v.x = tf32r(v.x); v.y = tf32r(v.y); v.z = tf32r(v.z); v.w = tf32r(v.w);
        b[i] = v;
    }
}

// edge_index is int32 (JAX x64 disabled downcasts int64 -> int32)
__global__ void build_edges(const int* __restrict__ ei, int* __restrict__ src,
                            int* __restrict__ dst, int* __restrict__ deg, int E, int N) {
    int e = blockIdx.x * blockDim.x + threadIdx.x;
    int ET = E + N;
    if (e >= ET) return;
    int s, d;
    if (e < E) { s = ei[2 * e]; d = ei[2 * e + 1]; }
    else       { s = d = e - E; }
    src[e] = s;
    dst[e] = d;
    atomicAdd(&deg[d], 1);
}

__global__ void scan_excl(const int* __restrict__ deg, int* __restrict__ off, int n) {
    __shared__ int sh[1024];
    __shared__ int carry;
    if (threadIdx.x == 0) carry = 0;
    __syncthreads();
    for (int base = 0; base < n; base += 1024) {
        int i = base + threadIdx.x;
        int v = (i < n) ? deg[i] : 0;
        sh[threadIdx.x] = v;
        __syncthreads();
        #pragma unroll
        for (int ofs = 1; ofs < 1024; ofs <<= 1) {
            int t = (threadIdx.x >= ofs) ? sh[threadIdx.x - ofs] : 0;
            __syncthreads();
            sh[threadIdx.x] += t;
            __syncthreads();
        }
        if (i < n) off[i] = carry + sh[threadIdx.x] - v;
        __syncthreads();
        if (threadIdx.x == 1023) carry += sh[1023];
        __syncthreads();
    }
    if (threadIdx.x == 0) off[n] = carry;
}

__global__ void fill_csr(const int* __restrict__ dst, const int* __restrict__ off,
                         int* __restrict__ cur, int* __restrict__ csr, int ET) {
    int e = blockIdx.x * blockDim.x + threadIdx.x;
    if (e >= ET) return;
    int d = dst[e];
    int p = off[d] + atomicAdd(&cur[d], 1);
    csr[p] = e;
}

// ------------------------- tf32 tensor-core GEMM -------------------------
// C(MxN) = A(MxK) @ B(KxN) + bias, optional ReLU. Inputs pre-rounded to tf32.
// 128x128x32 CTA tile, 256 threads (8 warps of 64x32), 3-stage cp.async,
// 106KB smem -> 2 CTAs/SM.
#define BM 128
#define BN 128
#define BK 32
#define LDA 36            // %32 == 4 -> conflict-free A frag reads
#define LDB 132           // %32 == 4 -> conflict-free B frag reads
#define ASTAGE (BM * LDA)
#define BSTAGE (BK * LDB)
#define SSTAGE (ASTAGE + BSTAGE)
#define NSTAGES 3
#define GEMM_SMEM_BYTES (SSTAGE * NSTAGES * 4)

__device__ __forceinline__ void cp16(uint32_t saddr, const float* g, bool valid) {
    int sz = valid ? 16 : 0;
    asm volatile("cp.async.cg.shared.global [%0], [%1], 16, %2;\n"
                 :: "r"(saddr), "l"(g), "r"(sz));
}

__device__ __forceinline__ void mma_tf32(float* c, const uint32_t* a, uint32_t b0, uint32_t b1) {
    asm volatile(
        "mma.sync.aligned.m16n8k8.row.col.f32.tf32.tf32.f32 "
        "{%0,%1,%2,%3}, {%4,%5,%6,%7}, {%8,%9}, {%0,%1,%2,%3};\n"
        : "+f"(c[0]), "+f"(c[1]), "+f"(c[2]), "+f"(c[3])
        : "r"(a[0]), "r"(a[1]), "r"(a[2]), "r"(a[3]), "r"(b0), "r"(b1));
}

template <bool RELU>
__global__ __launch_bounds__(256, 2)
void gemm_tf32(const float* __restrict__ A, const float* __restrict__ B,
               const float* __restrict__ bias, float* __restrict__ C,
               int M, int N, int K) {
    extern __shared__ float sm[];
    int tid  = threadIdx.x;
    int warp = tid >> 5;
    int lane = tid & 31;
    int g = lane >> 2;
    int t = lane & 3;
    int wm = warp >> 2;       // 0..1
    int wn = warp & 3;        // 0..3
    int mbase = wm * 64;
    int nbase = wn * 32;
    int am0 = blockIdx.y * BM;
    int bn0 = blockIdx.x * BN;
    int NIT = (K + BK - 1) / BK;

    float acc[4][4][4];
    #pragma unroll
    for (int i = 0; i < 4; i++)
        #pragma unroll
        for (int j = 0; j < 4; j++)
            #pragma unroll
            for (int k = 0; k < 4; k++) acc[i][j][k] = 0.0f;

    uint32_t smbase = (uint32_t)__cvta_generic_to_shared(sm);

    auto load_stage = [&](int it, int st) {
        int kt = it * BK;
        uint32_t as = smbase + (uint32_t)(st * SSTAGE) * 4u;
        uint32_t bs = as + (uint32_t)ASTAGE * 4u;
        // A: 128 rows x 8 float4
        #pragma unroll
        for (int i = 0; i < 4; i++) {
            int idx = tid + i * 256;
            int r  = idx >> 3;
            int c4 = (idx & 7) * 4;
            bool v = (am0 + r < M) && (kt + c4 + 4 <= K);
            const float* gp = A + (size_t)(v ? (am0 + r) : 0) * K + (v ? (kt + c4) : 0);
            cp16(as + (uint32_t)(r * LDA + c4) * 4u, gp, v);
        }
        // B: 32 rows x 32 float4
        #pragma unroll
        for (int i = 0; i < 4; i++) {
            int idx = tid + i * 256;
            int r  = idx >> 5;
            int c4 = (idx & 31) * 4;
            bool v = (kt + r < K) && (bn0 + c4 + 4 <= N);
            const float* gp = B + (size_t)(v ? (kt + r) : 0) * N + (v ? (bn0 + c4) : 0);
            cp16(bs + (uint32_t)(r * LDB + c4) * 4u, gp, v);
        }
        asm volatile("cp.async.commit_group;\n");
    };

    load_stage(0, 0);
    if (NIT > 1) load_stage(1, 1);

    for (int it = 0; it < NIT; it++) {
        asm volatile("cp.async.wait_group 1;\n");
        __syncthreads();
        if (it + 2 < NIT) load_stage(it + 2, (it + 2) % NSTAGES);

        const float* As = sm + (it % NSTAGES) * SSTAGE;
        const float* Bs = As + ASTAGE;

        #pragma unroll
        for (int kk = 0; kk < BK; kk += 8) {
            uint32_t a[4][4];
            #pragma unroll
            for (int mf = 0; mf < 4; mf++) {
                int r = mbase + mf * 16 + g;
                a[mf][0] = __float_as_uint(As[r * LDA + kk + t]);
                a[mf][1] = __float_as_uint(As[(r + 8) * LDA + kk + t]);
                a[mf][2] = __float_as_uint(As[r * LDA + kk + t + 4]);
                a[mf][3] = __float_as_uint(As[(r + 8) * LDA + kk + t + 4]);
            }
            #pragma unroll
            for (int nf = 0; nf < 4; nf++) {
                int ccol = nbase + nf * 8 + g;
                uint32_t b0 = __float_as_uint(Bs[(kk + t) * LDB + ccol]);
                uint32_t b1 = __float_as_uint(Bs[(kk + t + 4) * LDB + ccol]);
                #pragma unroll
                for (int mf = 0; mf < 4; mf++)
                    mma_tf32(acc[mf][nf], a[mf], b0, b1);
            }
        }
        __syncthreads();
    }

    #pragma unroll
    for (int mf = 0; mf < 4; mf++) {
        int row0 = am0 + mbase + mf * 16 + g;
        int row1 = row0 + 8;
        #pragma unroll
        for (int nf = 0; nf < 4; nf++) {
            int col = bn0 + nbase + nf * 8 + 2 * t;
            if (col >= N) continue;
            float2 bv = *(const float2*)(bias + col);
            if (row0 < M) {
                float v0 = acc[mf][nf][0] + bv.x;
                float v1 = acc[mf][nf][1] + bv.y;
                if (RELU) { v0 = fmaxf(v0, 0.f); v1 = fmaxf(v1, 0.f); }
                *(float2*)(C + (size_t)row0 * N + col) = make_float2(v0, v1);
            }
            if (row1 < M) {
                float v2 = acc[mf][nf][2] + bv.x;
                float v3 = acc[mf][nf][3] + bv.y;
                if (RELU) { v2 = fmaxf(v2, 0.f); v3 = fmaxf(v3, 0.f); }
                *(float2*)(C + (size_t)row1 * N + col) = make_float2(v2, v3);
            }
        }
    }
}

// ------------------------- fused GATv2: alpha + softmax + aggregate ------------
// One block per dst node. Pass 1 is WARP-parallel over incoming edges (no
// per-edge block barriers); xr[dst] and att staged in smem. Then softmax stats,
// then block-parallel weighted aggregation with head-mean + bias.
__global__ __launch_bounds__(256)
void gat_fused(const float* __restrict__ xl, const float* __restrict__ xr,
               const int* __restrict__ off, const int* __restrict__ csr,
               const int* __restrict__ src, const float* __restrict__ att,
               const float* __restrict__ gat_bias, float* __restrict__ alpha_s,
               float* __restrict__ outm, int N) {
    int n = blockIdx.x;
    if (n >= N) return;
    int t = threadIdx.x;
    int lane = t & 31, wid = t >> 5;
    int b = off[n], e2 = off[n + 1];

    __shared__ float s_xr[4096];
    __shared__ float s_att[4096];
    __shared__ float sm_m[N_HEADS], sm_inv[N_HEADS];

    const float4* xrp = (const float4*)(xr + (size_t)n * 4096);
    const float4* atp = (const float4*)att;
    #pragma unroll
    for (int j = 0; j < 4; j++) {
        int idx = t + j * 256;
        ((float4*)s_xr)[idx]  = xrp[idx];
        ((float4*)s_att)[idx] = atp[idx];
    }
    __syncthreads();

    // ---- pass 1: logits, one warp per edge ----
    for (int i = b + wid; i < e2; i += 8) {
        int s = src[csr[i]];
        const float* pl = xl + (size_t)s * 4096;
        float part[N_HEADS];
        #pragma unroll
        for (int h = 0; h < N_HEADS; h++) {
            float p = 0.0f;
            int base = h * 1024;
            #pragma unroll 8
            for (int k = 0; k < 32; k++) {
                int c = base + lane + k * 32;
                float v = pl[c] + s_xr[c];
                v = (v > 0.0f) ? v : NSLOPE * v;
                p += v * s_att[c];
            }
            part[h] = p;
        }
        #pragma unroll
        for (int h = 0; h < N_HEADS; h++) {
            float v = part[h];
            #pragma unroll
            for (int o = 16; o; o >>= 1) v += __shfl_xor_sync(0xffffffffu, v, o);
            if (lane == 0) alpha_s[(size_t)i * N_HEADS + h] = v;
        }
    }
    __syncthreads();

    // ---- softmax stats (4 threads, serial over deg — avg deg ~5) ----
    if (t < N_HEADS) {
        float m = -1e30f;
        for (int i = b; i < e2; i++)
            m = fmaxf(m, alpha_s[(size_t)i * N_HEADS + t]);
        float z = 0.0f;
        for (int i = b; i < e2; i++)
            z += __expf(alpha_s[(size_t)i * N_HEADS + t] - m);
        sm_m[t] = m;
        sm_inv[t] = 1.0f / (z + 1e-16f);
    }
    __syncthreads();
    float mf0 = sm_m[0], mf1 = sm_m[1], mf2 = sm_m[2], mf3 = sm_m[3];
    float iv0 = sm_inv[0], iv1 = sm_inv[1], iv2 = sm_inv[2], iv3 = sm_inv[3];

    // ---- pass 2: weighted aggregation (block-parallel over channels) ----
    float acc[16];
    #pragma unroll
    for (int j = 0; j < 16; j++) acc[j] = 0.0f;

    for (int i = b; i < e2; i++) {
        int s = src[csr[i]];
        const float* pl = xl + (size_t)s * 4096;
        const float* ap = alpha_s + (size_t)i * N_HEADS;
        float w0 = __expf(ap[0] - mf0) * iv0;
        float w1 = __expf(ap[1] - mf1) * iv1;
        float w2 = __expf(ap[2] - mf2) * iv2;
        float w3 = __expf(ap[3] - mf3) * iv3;
        #pragma unroll
        for (int j = 0; j < 4; j++) {
            int c = t + j * 256;
            acc[j]      += w0 * pl[c];
            acc[j + 4]  += w1 * pl[1024 + c];
            acc[j + 8]  += w2 * pl[2048 + c];
            acc[j + 12] += w3 * pl[3072 + c];
        }
    }

    #pragma unroll
    for (int jc = 0; jc < 4; jc++) {
        int c = t + jc * 256;
        float v = 0.25f * (acc[jc] + acc[jc + 4] + acc[jc + 8] + acc[jc + 12]);
        outm[(size_t)n * 1024 + c] = v + gat_bias[c];
    }
}

// ------------------------- host orchestration -------------------------
static inline dim3 gemm_grid(int M, int N) {
    return dim3((N + BN - 1) / BN, (M + BM - 1) / BM);
}

extern "C" void kernel_launch(void* const* d_in, const int* in_sizes, int n_in,
                              void* d_out, int out_size) {
    const float* x    = (const float*)d_in[0];
    const float* emb  = (const float*)d_in[1];
    const int*   ei   = (const int*)d_in[2];
    const float* exps = (const float*)d_in[3];
    const float* W1   = (const float*)d_in[4];
    const float* b1   = (const float*)d_in[5];
    const float* W2   = (const float*)d_in[6];
    const float* b2   = (const float*)d_in[7];
    const float* Wl   = (const float*)d_in[8];
    const float* bl   = (const float*)d_in[9];
    const float* Wr   = (const float*)d_in[10];
    const float* br   = (const float*)d_in[11];
    const float* att  = (const float*)d_in[12];
    const float* gb   = (const float*)d_in[13];
    const float* Wfc  = (const float*)d_in[14];
    const float* bfc  = (const float*)d_in[15];

    int Nx = in_sizes[0] / 400;
    int Nc = in_sizes[1] / 1024;
    int E  = in_sizes[2] / 2;
    int N  = Nx + Nc;
    int ET = E + N;

    float *xin, *xh, *xc, *xl, *xr, *outm, *alpha, *wbuf;
    int *src, *dst, *deg, *off, *cur, *csr;
    cudaGetSymbolAddress((void**)&xin,   g_xin);
    cudaGetSymbolAddress((void**)&xh,    g_xh);
    cudaGetSymbolAddress((void**)&xc,    g_xc);
    cudaGetSymbolAddress((void**)&xl,    g_xl);
    cudaGetSymbolAddress((void**)&xr,    g_xr);
    cudaGetSymbolAddress((void**)&outm,  g_outm);
    cudaGetSymbolAddress((void**)&alpha, g_alpha);
    cudaGetSymbolAddress((void**)&wbuf,  g_wbuf);
    cudaGetSymbolAddress((void**)&src,   g_src);
    cudaGetSymbolAddress((void**)&dst,   g_dst);
    cudaGetSymbolAddress((void**)&deg,   g_deg);
    cudaGetSymbolAddress((void**)&off,   g_off);
    cudaGetSymbolAddress((void**)&cur,   g_cur);
    cudaGetSymbolAddress((void**)&csr,   g_csr);

    cudaFuncSetAttribute(gemm_tf32<true>,  cudaFuncAttributeMaxDynamicSharedMemorySize, GEMM_SMEM_BYTES);
    cudaFuncSetAttribute(gemm_tf32<false>, cudaFuncAttributeMaxDynamicSharedMemorySize, GEMM_SMEM_BYTES);

    // ---- MLP (launch order puts gemm #2 in the ncu -s 5 -c 1 window) ----
    round_tf32_copy4<<<(Nx * 100 + 255) / 256, 256>>>((const float4*)x, (float4*)xin, Nx * 100);
    round_tf32_copy4<<<(400 * 128 + 255) / 256, 256>>>((const float4*)W1, (float4*)wbuf, 400 * 128);
    gemm_tf32<true><<<gemm_grid(Nx, 512), 256, GEMM_SMEM_BYTES>>>(xin, wbuf, b1, xh, Nx, 512, 400);

    round_tf32_inplace4<<<(Nx * 128 + 255) / 256, 256>>>((float4*)xh, Nx * 128);
    round_tf32_copy4<<<(512 * 256 + 255) / 256, 256>>>((const float4*)W2, (float4*)wbuf, 512 * 256);
    gemm_tf32<false><<<gemm_grid(Nx, 1024), 256, GEMM_SMEM_BYTES>>>(xh, wbuf, b2, xc + (size_t)Nc * 1024, Nx, 1024, 512);

    // ---- concat + round xc ----
    copy_f4<<<(Nc * 256 + 255) / 256, 256>>>((const float4*)emb, (float4*)xc, Nc * 256);
    round_tf32_inplace4<<<(N * 256 + 255) / 256, 256>>>((float4*)xc, N * 256);

    // ---- projections xl, xr ----
    round_tf32_copy4<<<(1024 * 1024 + 255) / 256, 256>>>((const float4*)Wl, (float4*)wbuf, 1024 * 1024);
    gemm_tf32<false><<<gemm_grid(N, 4096), 256, GEMM_SMEM_BYTES>>>(xc, wbuf, bl, xl, N, 4096, 1024);
    round_tf32_copy4<<<(1024 * 1024 + 255) / 256, 256>>>((const float4*)Wr, (float4*)wbuf, 1024 * 1024);
    gemm_tf32<false><<<gemm_grid(N, 4096), 256, GEMM_SMEM_BYTES>>>(xc, wbuf, br, xr, N, 4096, 1024);

    // ---- graph structure (overlap-friendly: needed only by gat_fused) ----
    zero_int2<<<(N + 255) / 256, 256>>>(deg, cur, N);
    build_edges<<<(ET + 255) / 256, 256>>>(ei, src, dst, deg, E, N);
    scan_excl<<<1, 1024>>>(deg, off, N);
    fill_csr<<<(ET + 255) / 256, 256>>>(dst, off, cur, csr, ET);

    // ---- fused GATv2 ----
    gat_fused<<<N, 256>>>(xl, xr, off, csr, src, att, gb, alpha, outm, N);

    // ---- final FC + passthrough ----
    round_tf32_inplace4<<<(N * 256 + 255) / 256, 256>>>((float4*)outm, N * 256);
    round_tf32_copy4<<<(1024 * 115 + 255) / 256, 256>>>((const float4*)Wfc, (float4*)wbuf, 1024 * 115);
    gemm_tf32<false><<<gemm_grid(N, 460), 256, GEMM_SMEM_BYTES>>>(outm, wbuf, bfc, (float*)d_out, N, 460, 1024);

    copy_f4<<<(Nx * 115 + 255) / 256, 256>>>((const float4*)exps,
                                             (float4*)((float*)d_out + (size_t)N * 460),
                                             Nx * 115);
}